// round 3
// baseline (speedup 1.0000x reference)
#include <cuda_runtime.h>
#include <cstdint>

#define Nn 128
#define Tt 512
#define Dd 512
#define Hh 512
#define H4 2048
#define Mm 16
#define BK 64

// ---------------- device scratch (no allocations allowed) ----------------
__device__ float g_AW[Mm * H4 * Nn];   // [m][c][n]  = 16*2048*128 floats (16 MB)
__device__ float g_W[Mm * Nn];         // softmax weights [m][n]
__device__ float g_Hn[2][Nn * Hh];     // h, n-major  [n][h]
__device__ float g_HT[2][Hh * Nn];     // h, h-major  [h][n]
__device__ float g_CT[2][Hh * Nn];     // c, h-major  [h][n]
__device__ unsigned g_cnt = 0;
__device__ unsigned g_gen = 0;

// ---------------- helpers ----------------
__device__ __forceinline__ float2 ffma2(float2 a, float2 b, float2 c) {
    float2 d;
    asm("{\n\t"
        ".reg .b64 ra, rb, rc, rd;\n\t"
        "mov.b64 ra, {%2, %3};\n\t"
        "mov.b64 rb, {%4, %5};\n\t"
        "mov.b64 rc, {%6, %7};\n\t"
        "fma.rn.f32x2 rd, ra, rb, rc;\n\t"
        "mov.b64 {%0, %1}, rd;\n\t"
        "}"
        : "=f"(d.x), "=f"(d.y)
        : "f"(a.x), "f"(a.y), "f"(b.x), "f"(b.y), "f"(c.x), "f"(c.y));
    return d;
}

__device__ __forceinline__ float sigmoidf_(float v) {
    return 1.0f / (1.0f + __expf(-v));
}

// Grid barrier: all 128 CTAs are co-resident (128 <= 148 SMs, 1 CTA/SM), so
// spinning is deadlock-free. Generation-based, survives graph replays.
__device__ __forceinline__ void grid_sync() {
    __syncthreads();
    if (threadIdx.x == 0) {
        __threadfence();
        unsigned gen = *((volatile unsigned*)&g_gen);
        unsigned ticket = atomicAdd(&g_cnt, 1u);
        if (ticket == Nn - 1) {
            atomicExch(&g_cnt, 0u);
            __threadfence();
            atomicAdd(&g_gen, 1u);
        } else {
            while (*((volatile unsigned*)&g_gen) == gen) { __nanosleep(32); }
        }
        __threadfence();
    }
    __syncthreads();
}

// ---------------- kernel 1: AW[m][c][n] = sum_h Aflat[n][h][m] * Wattn[h][c] ----
__global__ void __launch_bounds__(256) aw_kernel(const float* __restrict__ A,
                                                 const float* __restrict__ Wattn) {
    __shared__ float As[512];        // 32 h-rows x 16 m
    __shared__ float Ws[32 * 128];   // 32 h-rows x 128 c
    const int tid = threadIdx.x;
    const int ct = blockIdx.x;       // col tile (0..15)
    const int n  = blockIdx.y;       // batch
    const int tx = tid & 31, ty = tid >> 5;
    const int m0 = ty * 2, c0 = tx * 4;

    float2 acc[2][2];
    #pragma unroll
    for (int i = 0; i < 2; i++)
        #pragma unroll
        for (int jj = 0; jj < 2; jj++) acc[i][jj] = make_float2(0.f, 0.f);

    for (int h0 = 0; h0 < Hh; h0 += 32) {
        const float* srcA = A + (size_t)n * (Hh * 16) + h0 * 16;
        As[tid] = srcA[tid];
        As[tid + 256] = srcA[tid + 256];
        #pragma unroll
        for (int j4 = 0; j4 < 4; j4++) {
            int fi = tid + j4 * 256;               // 0..1023 float4 slots
            int r = fi >> 5, c4 = fi & 31;
            *(float4*)&Ws[r * 128 + c4 * 4] =
                *(const float4*)(Wattn + (size_t)(h0 + r) * H4 + ct * 128 + c4 * 4);
        }
        __syncthreads();
        #pragma unroll
        for (int k = 0; k < 32; k++) {
            float2 am = *(float2*)&As[k * 16 + m0];
            float4 wv = *(float4*)&Ws[k * 128 + c0];
            float2 a0 = make_float2(am.x, am.x);
            float2 a1 = make_float2(am.y, am.y);
            acc[0][0] = ffma2(a0, make_float2(wv.x, wv.y), acc[0][0]);
            acc[0][1] = ffma2(a0, make_float2(wv.z, wv.w), acc[0][1]);
            acc[1][0] = ffma2(a1, make_float2(wv.x, wv.y), acc[1][0]);
            acc[1][1] = ffma2(a1, make_float2(wv.z, wv.w), acc[1][1]);
        }
        __syncthreads();
    }
    #pragma unroll
    for (int im = 0; im < 2; im++) {
        int m = m0 + im;
        float v[4] = {acc[im][0].x, acc[im][0].y, acc[im][1].x, acc[im][1].y};
        #pragma unroll
        for (int jc = 0; jc < 4; jc++)
            g_AW[((size_t)m * H4 + ct * 128 + c0 + jc) * Nn + n] = v[jc];
    }
}

// ---------------- kernel 2: h0 = c0 = mean_m Aflat[n][h][m] ----------------
__global__ void __launch_bounds__(256) init_kernel(const float* __restrict__ A) {
    int idx = blockIdx.x * 256 + threadIdx.x;  // 0..65535
    int n = idx >> 9, h = idx & 511;
    const float4* p = (const float4*)(A + (size_t)n * (Hh * 16) + h * 16);
    float4 a = p[0], b = p[1], c = p[2], d = p[3];
    float s = a.x + a.y + a.z + a.w + b.x + b.y + b.z + b.w +
              c.x + c.y + c.z + c.w + d.x + d.y + d.z + d.w;
    float v = s * 0.0625f;
    g_Hn[0][n * Hh + h] = v;
    g_HT[0][h * Nn + n] = v;
    g_CT[0][h * Nn + n] = v;
}

// ---------------- kernel 3: persistent recurrent kernel ----------------
__global__ void __launch_bounds__(256, 1) rnn_kernel(
    const float* __restrict__ x, const float* __restrict__ A,
    const float* __restrict__ Wx, const float* __restrict__ Wh,
    const float* __restrict__ b4, float* __restrict__ out) {

    __shared__ float Xs[BK * 132];    // activation tile [k][n], padded; reused as gate smem
    __shared__ float WsT[16 * 68];    // weight tile transposed [cc][k]
    __shared__ float wsm[Mm * 128];   // softmax weights [m][n]
    __shared__ float red[8 * 16];     // per-warp score partials

    const int tid = threadIdx.x;
    const int bid = blockIdx.x;       // 0..127
    const int n_own = bid;
    const int lane = tid & 31, wrp = tid >> 5;

    // Phase A: this thread's 2 rows of Aflat[n_own], register-resident forever
    float Ar[2][16];
    {
        const float* pA = A + (size_t)n_own * (Hh * 16) + (2 * tid) * 16;
        #pragma unroll
        for (int i = 0; i < 16; i++) { Ar[0][i] = pA[i]; Ar[1][i] = pA[16 + i]; }
    }

    // Phase B mapping: 16 gate columns = 4 gates x 4 hidden cols
    const int tx = tid & 15;
    const int ty = tid >> 4;
    const int n0 = ty * 8;
    const int q = tx >> 2, j = tx & 3;
    const int c = q * 512 + bid * 4 + j;
    const float bb = b4[c];
    const float inv_sqrt_h = 0.04419417382415922f;   // 1/sqrt(512)

    for (int t = 0; t < Tt; t++) {
        const int p = t & 1;

        // ================= Phase A: softmax attention weights =================
        float2 hv = *(const float2*)&g_Hn[p][n_own * Hh + 2 * tid];
        float part[16];
        #pragma unroll
        for (int m = 0; m < 16; m++)
            part[m] = hv.x * Ar[0][m] + hv.y * Ar[1][m];
        #pragma unroll
        for (int off = 16; off; off >>= 1)
            #pragma unroll
            for (int m = 0; m < 16; m++)
                part[m] += __shfl_xor_sync(0xffffffffu, part[m], off);
        if (lane == 0) {
            #pragma unroll
            for (int m = 0; m < 16; m++) red[wrp * 16 + m] = part[m];
        }
        __syncthreads();
        float sc[16];
        #pragma unroll
        for (int m = 0; m < 16; m++) {
            float s = 0.f;
            #pragma unroll
            for (int w = 0; w < 8; w++) s += red[w * 16 + m];
            sc[m] = s * inv_sqrt_h;
        }
        float mx = sc[0];
        #pragma unroll
        for (int m = 1; m < 16; m++) mx = fmaxf(mx, sc[m]);
        float se = 0.f;
        #pragma unroll
        for (int m = 0; m < 16; m++) { sc[m] = __expf(sc[m] - mx); se += sc[m]; }
        float inv = 1.0f / se;
        if (tid < 16) g_W[tid * Nn + n_own] = sc[tid] * inv;

        grid_sync();   // w visible to all; all h reads done before h overwritten

        // ================= Phase B: fused GEMM + gates =================
        #pragma unroll
        for (int i2 = 0; i2 < 8; i2++) wsm[tid + i2 * 256] = g_W[tid + i2 * 256];

        float2 acc[4];
        #pragma unroll
        for (int pp = 0; pp < 4; pp++) acc[pp] = make_float2(bb, bb);

        __syncthreads();   // wsm + red-reuse safety

        // attention contribution via precomputed AW: K = 16
        #pragma unroll
        for (int m = 0; m < 16; m++) {
            const float* ap = g_AW + ((size_t)m * H4 + c) * Nn + n0;
            float4 aw0 = *(const float4*)ap;
            float4 aw1 = *(const float4*)(ap + 4);
            float4 w0 = *(float4*)&wsm[m * 128 + n0];
            float4 w1 = *(float4*)&wsm[m * 128 + n0 + 4];
            acc[0] = ffma2(make_float2(aw0.x, aw0.y), make_float2(w0.x, w0.y), acc[0]);
            acc[1] = ffma2(make_float2(aw0.z, aw0.w), make_float2(w0.z, w0.w), acc[1]);
            acc[2] = ffma2(make_float2(aw1.x, aw1.y), make_float2(w1.x, w1.y), acc[2]);
            acc[3] = ffma2(make_float2(aw1.z, aw1.w), make_float2(w1.z, w1.w), acc[3]);
        }

        // x @ Wx (part 0) and h @ Wh (part 1), K = 512 each
        #pragma unroll 1
        for (int prt = 0; prt < 2; prt++) {
            const float* Wmat = (prt == 0) ? Wx : Wh;
            #pragma unroll 1
            for (int k0 = 0; k0 < 512; k0 += BK) {
                __syncthreads();
                if (prt == 0) {
                    int nn = tid >> 1, kh = (tid & 1) * 32;
                    const float* src = x + ((size_t)nn * Tt + t) * Dd + k0 + kh;
                    #pragma unroll
                    for (int i4 = 0; i4 < 8; i4++) {
                        float4 v = *(const float4*)(src + i4 * 4);
                        Xs[(kh + i4 * 4 + 0) * 132 + nn] = v.x;
                        Xs[(kh + i4 * 4 + 1) * 132 + nn] = v.y;
                        Xs[(kh + i4 * 4 + 2) * 132 + nn] = v.z;
                        Xs[(kh + i4 * 4 + 3) * 132 + nn] = v.w;
                    }
                } else {
                    const float* src = g_HT[p] + k0 * Nn;
                    #pragma unroll
                    for (int i4 = 0; i4 < 8; i4++) {
                        int fi = tid + i4 * 256;            // 0..2047 float4 slots
                        int r = fi >> 5, c4 = (fi & 31) * 4;  // r 0..63
                        *(float4*)&Xs[r * 132 + c4] = *(const float4*)(src + r * Nn + c4);
                    }
                }
                {
                    int kk = tid & 63, ccb = (tid >> 6) * 4;
                    int qq = ccb >> 2;
                    float4 wv = *(const float4*)(Wmat + (size_t)(k0 + kk) * H4 + qq * 512 + bid * 4);
                    WsT[(ccb + 0) * 68 + kk] = wv.x;
                    WsT[(ccb + 1) * 68 + kk] = wv.y;
                    WsT[(ccb + 2) * 68 + kk] = wv.z;
                    WsT[(ccb + 3) * 68 + kk] = wv.w;
                }
                __syncthreads();
                #pragma unroll 4
                for (int k4 = 0; k4 < BK / 4; k4++) {
                    float4 wq = *(float4*)&WsT[tx * 68 + k4 * 4];
                    float wk[4] = {wq.x, wq.y, wq.z, wq.w};
                    #pragma unroll
                    for (int kk = 0; kk < 4; kk++) {
                        int k = k4 * 4 + kk;
                        float4 v0 = *(float4*)&Xs[k * 132 + n0];
                        float4 v1 = *(float4*)&Xs[k * 132 + n0 + 4];
                        float2 wd = make_float2(wk[kk], wk[kk]);
                        acc[0] = ffma2(make_float2(v0.x, v0.y), wd, acc[0]);
                        acc[1] = ffma2(make_float2(v0.z, v0.w), wd, acc[1]);
                        acc[2] = ffma2(make_float2(v1.x, v1.y), wd, acc[2]);
                        acc[3] = ffma2(make_float2(v1.z, v1.w), wd, acc[3]);
                    }
                }
            }
        }

        // ---- epilogue: exchange gates through smem (reuse Xs), combine ----
        __syncthreads();
        float* gsm = Xs;   // [16][132]
        *(float4*)&gsm[tx * 132 + n0]     = make_float4(acc[0].x, acc[0].y, acc[1].x, acc[1].y);
        *(float4*)&gsm[tx * 132 + n0 + 4] = make_float4(acc[2].x, acc[2].y, acc[3].x, acc[3].y);
        __syncthreads();
        #pragma unroll
        for (int e = 0; e < 2; e++) {
            int idx2 = tid + e * 256;               // 0..511
            int nn = idx2 & 127, jj = idx2 >> 7;    // 4 hcols x 128 n
            float iv = gsm[(0 * 4 + jj) * 132 + nn];
            float fv = gsm[(1 * 4 + jj) * 132 + nn];
            float ov = gsm[(2 * 4 + jj) * 132 + nn];
            float gv = gsm[(3 * 4 + jj) * 132 + nn];
            int hcol = bid * 4 + jj;
            float cold = g_CT[p][hcol * Nn + nn];
            float cn = sigmoidf_(fv) * cold + sigmoidf_(iv) * tanhf(gv);
            float hn = sigmoidf_(ov) * tanhf(cn);
            g_CT[p ^ 1][hcol * Nn + nn] = cn;
            g_HT[p ^ 1][hcol * Nn + nn] = hn;
            g_Hn[p ^ 1][nn * Hh + hcol] = hn;
            out[((size_t)nn * Tt + t) * Hh + hcol] = hn;
        }

        grid_sync();   // new h/c visible before next step's Phase A
    }
}

// ---------------- launcher ----------------
extern "C" void kernel_launch(void* const* d_in, const int* in_sizes, int n_in,
                              void* d_out, int out_size) {
    const float* x     = (const float*)d_in[0];
    const float* A     = (const float*)d_in[1];
    const float* Wx    = (const float*)d_in[2];
    const float* Wh    = (const float*)d_in[3];
    const float* Wattn = (const float*)d_in[4];
    const float* b     = (const float*)d_in[5];
    float* out = (float*)d_out;
    (void)in_sizes; (void)n_in; (void)out_size;

    aw_kernel<<<dim3(16, 128), 256>>>(A, Wattn);
    init_kernel<<<256, 256>>>(A);
    rnn_kernel<<<Nn, 256>>>(x, A, Wx, Wh, b, out);
}

// round 5
// speedup vs baseline: 1.1437x; 1.1437x over previous
#include <cuda_runtime.h>
#include <cstdint>

#define Nn 128
#define Tt 512
#define Dd 512
#define Hh 512
#define H4 2048
#define Mm 16
#define BK 128
#define KTOT 1024

typedef unsigned long long u64;

// ---------------- device scratch ----------------
__device__ float g_AW[Mm * H4 * Nn];     // [m][c][n]  (16 MB)
__device__ float g_WT[H4 * KTOT];        // [c][k] = [Wx;Wh]^T   (8 MB)
__device__ float g_W[Mm * Nn];           // softmax weights [m][n]
__device__ float g_Hn[2][Nn * Hh];       // h, n-major
__device__ float g_HT[2][Hh * Nn];       // h, h-major
__device__ float g_CT[2][Hh * Nn];       // c, h-major
__device__ unsigned g_cnt = 0;
__device__ unsigned g_gen = 0;

// ---------------- helpers ----------------
__device__ __forceinline__ u64 ffma2(u64 a, u64 b, u64 c) {
    u64 d;
    asm("fma.rn.f32x2 %0, %1, %2, %3;" : "=l"(d) : "l"(a), "l"(b), "l"(c));
    return d;
}
__device__ __forceinline__ u64 splat2(float w) {
    u64 d; asm("mov.b64 %0, {%1, %1};" : "=l"(d) : "f"(w)); return d;
}
__device__ __forceinline__ float sigmoidf_(float v) {
    return 1.0f / (1.0f + __expf(-v));
}

// Grid barrier: 128 CTAs < 148 SMs -> all co-resident, spin is deadlock-free.
__device__ __forceinline__ void grid_sync() {
    __syncthreads();
    if (threadIdx.x == 0) {
        __threadfence();
        unsigned gen = *((volatile unsigned*)&g_gen);
        unsigned ticket = atomicAdd(&g_cnt, 1u);
        if (ticket == Nn - 1) {
            atomicExch(&g_cnt, 0u);
            __threadfence();
            atomicAdd(&g_gen, 1u);
        } else {
            while (*((volatile unsigned*)&g_gen) == gen) { __nanosleep(32); }
        }
        __threadfence();
    }
    __syncthreads();
}

// ---------------- kernel 1: AW[m][c][n] = sum_h Aflat[n][h][m] * Wattn[h][c] ----
__global__ void __launch_bounds__(256) aw_kernel(const float* __restrict__ A,
                                                 const float* __restrict__ Wattn) {
    __shared__ float As[512];
    __shared__ float Ws[32 * 128];
    const int tid = threadIdx.x;
    const int ct = blockIdx.x;
    const int n  = blockIdx.y;
    const int tx = tid & 31, ty = tid >> 5;
    const int m0 = ty * 2, c0 = tx * 4;

    float2 acc[2][2];
    #pragma unroll
    for (int i = 0; i < 2; i++)
        #pragma unroll
        for (int jj = 0; jj < 2; jj++) acc[i][jj] = make_float2(0.f, 0.f);

    for (int h0 = 0; h0 < Hh; h0 += 32) {
        const float* srcA = A + (size_t)n * (Hh * 16) + h0 * 16;
        As[tid] = srcA[tid];
        As[tid + 256] = srcA[tid + 256];
        #pragma unroll
        for (int j4 = 0; j4 < 4; j4++) {
            int fi = tid + j4 * 256;
            int r = fi >> 5, c4 = fi & 31;
            *(float4*)&Ws[r * 128 + c4 * 4] =
                *(const float4*)(Wattn + (size_t)(h0 + r) * H4 + ct * 128 + c4 * 4);
        }
        __syncthreads();
        #pragma unroll
        for (int k = 0; k < 32; k++) {
            float2 am = *(float2*)&As[k * 16 + m0];
            float4 wv = *(float4*)&Ws[k * 128 + c0];
            acc[0][0].x += am.x * wv.x; acc[0][0].y += am.x * wv.y;
            acc[0][1].x += am.x * wv.z; acc[0][1].y += am.x * wv.w;
            acc[1][0].x += am.y * wv.x; acc[1][0].y += am.y * wv.y;
            acc[1][1].x += am.y * wv.z; acc[1][1].y += am.y * wv.w;
        }
        __syncthreads();
    }
    #pragma unroll
    for (int im = 0; im < 2; im++) {
        int m = m0 + im;
        float v[4] = {acc[im][0].x, acc[im][0].y, acc[im][1].x, acc[im][1].y};
        #pragma unroll
        for (int jc = 0; jc < 4; jc++)
            g_AW[((size_t)m * H4 + ct * 128 + c0 + jc) * Nn + n] = v[jc];
    }
}

// ---------------- kernel 2: h0 = c0 = mean over Da*Da ----------------
__global__ void __launch_bounds__(256) init_kernel(const float* __restrict__ A) {
    int idx = blockIdx.x * 256 + threadIdx.x;
    int n = idx >> 9, h = idx & 511;
    const float4* p = (const float4*)(A + (size_t)n * (Hh * 16) + h * 16);
    float4 a = p[0], b = p[1], c = p[2], d = p[3];
    float s = a.x + a.y + a.z + a.w + b.x + b.y + b.z + b.w +
              c.x + c.y + c.z + c.w + d.x + d.y + d.z + d.w;
    float v = s * 0.0625f;
    g_Hn[0][n * Hh + h] = v;
    g_HT[0][h * Nn + n] = v;
    g_CT[0][h * Nn + n] = v;
}

// ---------------- kernel 3: transpose [Wx;Wh] -> g_WT[c][k] ----------------
__global__ void __launch_bounds__(256) wt_kernel(const float* __restrict__ Wx,
                                                 const float* __restrict__ Wh) {
    __shared__ float tbuf[32][33];
    const int c0 = blockIdx.x * 32;
    const int k0 = blockIdx.y * 32;
    const int tx = threadIdx.x & 31, ty = threadIdx.x >> 5;
    #pragma unroll
    for (int i = 0; i < 4; i++) {
        int k = k0 + ty + i * 8;
        float v = (k < 512) ? Wx[(size_t)k * H4 + c0 + tx]
                            : Wh[(size_t)(k - 512) * H4 + c0 + tx];
        tbuf[ty + i * 8][tx] = v;
    }
    __syncthreads();
    #pragma unroll
    for (int i = 0; i < 4; i++) {
        int c = c0 + ty + i * 8;
        g_WT[(size_t)c * KTOT + k0 + tx] = tbuf[tx][ty + i * 8];
    }
}

// ---------------- kernel 4: persistent recurrent kernel ----------------
// dynamic smem layout (floats):
//   Xs  [BK*132]      : 0        .. 16896     (67.6 KB) ; reused as gate smem
//   WsT [16*132]      : 16896    .. 19008     (8.4 KB)
//   wsm [16*128]      : 19008    .. 21056     (8 KB)
//   red [128]         : 21056    .. 21184
#define OFF_WST 16896
#define OFF_WSM 19008
#define OFF_RED 21056
#define SMEM_BYTES (21184 * 4)

__global__ void __launch_bounds__(256, 1) rnn_kernel(
    const float* __restrict__ x, const float* __restrict__ A,
    const float* __restrict__ b4, float* __restrict__ out) {

    extern __shared__ float sm[];
    float* Xs  = sm;
    float* WsT = sm + OFF_WST;
    float* wsm = sm + OFF_WSM;
    float* red = sm + OFF_RED;

    const int tid = threadIdx.x;
    const int bid = blockIdx.x;
    const int n_own = bid;
    const int lane = tid & 31, wrp = tid >> 5;

    // register-resident Aflat rows for Phase A
    float Ar[2][16];
    {
        const float* pA = A + (size_t)n_own * (Hh * 16) + (2 * tid) * 16;
        #pragma unroll
        for (int i = 0; i < 16; i++) { Ar[0][i] = pA[i]; Ar[1][i] = pA[16 + i]; }
    }

    // Phase B mapping: tx -> gate column (q = gate, j = hidden col), ty -> n block
    const int tx = tid & 15;
    const int ty = tid >> 4;
    const int n0 = ty * 8;
    const int q = tx >> 2, j = tx & 3;
    const int cg = q * 512 + bid * 4 + j;     // global column in [0,2048)
    const float bb = b4[cg];
    const float inv_sqrt_h = 0.04419417382415922f;  // 1/sqrt(512)

    for (int t = 0; t < Tt; t++) {
        const int p = t & 1;

        // ================= Phase A: softmax attention weights =================
        {
            float2 hv = *(const float2*)&g_Hn[p][n_own * Hh + 2 * tid];
            float part[16];
            #pragma unroll
            for (int m = 0; m < 16; m++)
                part[m] = hv.x * Ar[0][m] + hv.y * Ar[1][m];
            #pragma unroll
            for (int off = 16; off; off >>= 1)
                #pragma unroll
                for (int m = 0; m < 16; m++)
                    part[m] += __shfl_xor_sync(0xffffffffu, part[m], off);
            if (lane == 0) {
                #pragma unroll
                for (int m = 0; m < 16; m++) red[wrp * 16 + m] = part[m];
            }
            __syncthreads();
            if (tid < 16) {
                float sc[16];
                #pragma unroll
                for (int m = 0; m < 16; m++) {
                    float s = 0.f;
                    #pragma unroll
                    for (int w = 0; w < 8; w++) s += red[w * 16 + m];
                    sc[m] = s * inv_sqrt_h;
                }
                float mx = sc[0];
                #pragma unroll
                for (int m = 1; m < 16; m++) mx = fmaxf(mx, sc[m]);
                float se = 0.f;
                #pragma unroll
                for (int m = 0; m < 16; m++) { sc[m] = __expf(sc[m] - mx); se += sc[m]; }
                g_W[tid * Nn + n_own] = sc[tid] / se;
            }
        }
        // no grid sync here: main GEMM below does not depend on w.

        // ================= main GEMM: [x_t ; h] @ WT  (K = 1024) =============
        u64 acc[4];
        #pragma unroll
        for (int pp = 0; pp < 4; pp++) acc[pp] = splat2(bb);

        #pragma unroll 1
        for (int k0 = 0; k0 < KTOT; k0 += BK) {
            __syncthreads();   // previous tile fully consumed
            if (k0 < 512) {
                // x tile: transpose [n][k] -> Xs[k][n]
                int nn = tid >> 1, kh = (tid & 1) * 64;
                const float* src = x + ((size_t)nn * Tt + t) * Dd + k0 + kh;
                #pragma unroll
                for (int i = 0; i < 16; i++) {
                    float4 v = *(const float4*)(src + i * 4);
                    Xs[(kh + i * 4 + 0) * 132 + nn] = v.x;
                    Xs[(kh + i * 4 + 1) * 132 + nn] = v.y;
                    Xs[(kh + i * 4 + 2) * 132 + nn] = v.z;
                    Xs[(kh + i * 4 + 3) * 132 + nn] = v.w;
                }
            } else {
                // h tile: already [k][n]
                const float* src = g_HT[p] + (k0 - 512) * Nn;
                #pragma unroll
                for (int i = 0; i < 16; i++) {
                    int fi = tid + i * 256;
                    int r = fi >> 5, c4 = (fi & 31) * 4;
                    *(float4*)&Xs[r * 132 + c4] = *(const float4*)(src + r * Nn + c4);
                }
            }
            // weight tile: 16 columns x 128 k, coalesced from g_WT
            #pragma unroll
            for (int i = 0; i < 2; i++) {
                int fi = tid + i * 256;           // 512 float4 slots
                int rc = fi >> 5, k4 = (fi & 31) * 4;
                int cgl = (rc >> 2) * 512 + bid * 4 + (rc & 3);
                *(float4*)&WsT[rc * 132 + k4] =
                    *(const float4*)(g_WT + (size_t)cgl * KTOT + k0 + k4);
            }
            __syncthreads();
            #pragma unroll 4
            for (int k4 = 0; k4 < BK / 4; k4++) {
                float4 wq = *(float4*)&WsT[tx * 132 + k4 * 4];
                float wk[4] = {wq.x, wq.y, wq.z, wq.w};
                #pragma unroll
                for (int kk = 0; kk < 4; kk++) {
                    int k = k4 * 4 + kk;
                    u64 wd = splat2(wk[kk]);
                    ulonglong2 v0 = *(const ulonglong2*)&Xs[k * 132 + n0];
                    ulonglong2 v1 = *(const ulonglong2*)&Xs[k * 132 + n0 + 4];
                    acc[0] = ffma2(v0.x, wd, acc[0]);
                    acc[1] = ffma2(v0.y, wd, acc[1]);
                    acc[2] = ffma2(v1.x, wd, acc[2]);
                    acc[3] = ffma2(v1.y, wd, acc[3]);
                }
            }
        }

        grid_sync();   // sync1: all w written (skew absorbed by the GEMM above)

        // ---- attention contribution: K = 16, elementwise over n ----
        #pragma unroll
        for (int i2 = 0; i2 < 8; i2++) wsm[tid + i2 * 256] = g_W[tid + i2 * 256];
        __syncthreads();
        #pragma unroll
        for (int m = 0; m < 16; m++) {
            const float* ap = g_AW + ((size_t)m * H4 + cg) * Nn + n0;
            ulonglong2 aw0 = *(const ulonglong2*)ap;
            ulonglong2 aw1 = *(const ulonglong2*)(ap + 4);
            ulonglong2 w0 = *(const ulonglong2*)&wsm[m * 128 + n0];
            ulonglong2 w1 = *(const ulonglong2*)&wsm[m * 128 + n0 + 4];
            acc[0] = ffma2(aw0.x, w0.x, acc[0]);
            acc[1] = ffma2(aw0.y, w0.y, acc[1]);
            acc[2] = ffma2(aw1.x, w1.x, acc[2]);
            acc[3] = ffma2(aw1.y, w1.y, acc[3]);
        }

        // ---- epilogue: exchange gates via smem (reuse Xs), combine ----
        __syncthreads();                 // all attn reads of wsm done
        float* gsm = Xs;                 // [16][132]
        *(ulonglong2*)&gsm[tx * 132 + n0]     = make_ulonglong2(acc[0], acc[1]);
        *(ulonglong2*)&gsm[tx * 132 + n0 + 4] = make_ulonglong2(acc[2], acc[3]);
        __syncthreads();
        if (tid < 128) {
            int nn = tid;
            float hv4[4];
            #pragma unroll
            for (int jj = 0; jj < 4; jj++) {
                float iv = gsm[(0 + jj) * 132 + nn];
                float fv = gsm[(4 + jj) * 132 + nn];
                float ov = gsm[(8 + jj) * 132 + nn];
                float gv = gsm[(12 + jj) * 132 + nn];
                int hcol = bid * 4 + jj;
                float cold = g_CT[p][hcol * Nn + nn];
                float cn = sigmoidf_(fv) * cold + sigmoidf_(iv) * tanhf(gv);
                float hn = sigmoidf_(ov) * tanhf(cn);
                g_CT[p ^ 1][hcol * Nn + nn] = cn;
                g_HT[p ^ 1][hcol * Nn + nn] = hn;
                hv4[jj] = hn;
            }
            *(float4*)&g_Hn[p ^ 1][nn * Hh + bid * 4] = *(float4*)hv4;
            *(float4*)&out[((size_t)nn * Tt + t) * Hh + bid * 4] = *(float4*)hv4;
        }

        grid_sync();   // sync2: new h/c visible for next step
    }
}

// ---------------- launcher ----------------
extern "C" void kernel_launch(void* const* d_in, const int* in_sizes, int n_in,
                              void* d_out, int out_size) {
    const float* x     = (const float*)d_in[0];
    const float* A     = (const float*)d_in[1];
    const float* Wx    = (const float*)d_in[2];
    const float* Wh    = (const float*)d_in[3];
    const float* Wattn = (const float*)d_in[4];
    const float* b     = (const float*)d_in[5];
    float* out = (float*)d_out;
    (void)in_sizes; (void)n_in; (void)out_size;

    cudaFuncSetAttribute(rnn_kernel, cudaFuncAttributeMaxDynamicSharedMemorySize,
                         SMEM_BYTES);

    aw_kernel<<<dim3(16, 128), 256>>>(A, Wattn);
    wt_kernel<<<dim3(64, 32), 256>>>(Wx, Wh);
    init_kernel<<<256, 256>>>(A);
    rnn_kernel<<<Nn, 256, SMEM_BYTES>>>(x, A, b, out);
}

// round 6
// speedup vs baseline: 1.4823x; 1.2960x over previous
#include <cuda_runtime.h>
#include <cstdint>

#define Nn 128
#define Tt 512
#define Dd 512
#define Hh 512
#define H4 2048
#define Mm 16
#define BK 128
#define KTOT 1024

typedef unsigned long long u64;

// ---------------- device scratch ----------------
__device__ float g_AW[Mm * H4 * Nn];        // [m][c][n]  (16 MB)
__device__ u64   g_WT2[128 * KTOT * 16];    // [bid][k][16 cl] pre-splatted (16 MB)
__device__ float g_XT[(size_t)Tt * Dd * Nn];// [t][k][n]  (128 MB)
__device__ float g_W[Mm * Nn];              // softmax weights [m][n]
__device__ float g_Hn[2][Nn * Hh];          // h, n-major
__device__ float g_HT[2][Hh * Nn];          // h, h-major
__device__ float g_CT[2][Hh * Nn];          // c, h-major
__device__ unsigned g_cnt = 0;
__device__ unsigned g_gen = 0;

// ---------------- helpers ----------------
__device__ __forceinline__ u64 ffma2(u64 a, u64 b, u64 c) {
    u64 d;
    asm("fma.rn.f32x2 %0, %1, %2, %3;" : "=l"(d) : "l"(a), "l"(b), "l"(c));
    return d;
}
__device__ __forceinline__ u64 splat2(float w) {
    u64 d; asm("mov.b64 %0, {%1, %1};" : "=l"(d) : "f"(w)); return d;
}
__device__ __forceinline__ float sigmoidf_(float v) {
    return 1.0f / (1.0f + __expf(-v));
}
__device__ __forceinline__ void cpa16(uint32_t dst, const void* src) {
    asm volatile("cp.async.cg.shared.global [%0], [%1], 16;" :: "r"(dst), "l"(src));
}
__device__ __forceinline__ void cpa_commit() {
    asm volatile("cp.async.commit_group;");
}
__device__ __forceinline__ void cpa_wait0() {
    asm volatile("cp.async.wait_group 0;");
}

// Grid barrier: 128 CTAs < 148 SMs -> all co-resident, spin is deadlock-free.
__device__ __forceinline__ void grid_sync() {
    __syncthreads();
    if (threadIdx.x == 0) {
        __threadfence();
        unsigned gen = *((volatile unsigned*)&g_gen);
        unsigned ticket = atomicAdd(&g_cnt, 1u);
        if (ticket == Nn - 1) {
            atomicExch(&g_cnt, 0u);
            __threadfence();
            atomicAdd(&g_gen, 1u);
        } else {
            while (*((volatile unsigned*)&g_gen) == gen) { __nanosleep(32); }
        }
        __threadfence();
    }
    __syncthreads();
}

// ---------------- kernel 1: AW[m][c][n] = sum_h Aflat[n][h][m] * Wattn[h][c] ----
__global__ void __launch_bounds__(256) aw_kernel(const float* __restrict__ A,
                                                 const float* __restrict__ Wattn) {
    __shared__ float As[512];
    __shared__ float Ws[32 * 128];
    const int tid = threadIdx.x;
    const int ct = blockIdx.x;
    const int n  = blockIdx.y;
    const int tx = tid & 31, ty = tid >> 5;
    const int m0 = ty * 2, c0 = tx * 4;

    float2 acc[2][2];
    #pragma unroll
    for (int i = 0; i < 2; i++)
        #pragma unroll
        for (int jj = 0; jj < 2; jj++) acc[i][jj] = make_float2(0.f, 0.f);

    for (int h0 = 0; h0 < Hh; h0 += 32) {
        const float* srcA = A + (size_t)n * (Hh * 16) + h0 * 16;
        As[tid] = srcA[tid];
        As[tid + 256] = srcA[tid + 256];
        #pragma unroll
        for (int j4 = 0; j4 < 4; j4++) {
            int fi = tid + j4 * 256;
            int r = fi >> 5, c4 = fi & 31;
            *(float4*)&Ws[r * 128 + c4 * 4] =
                *(const float4*)(Wattn + (size_t)(h0 + r) * H4 + ct * 128 + c4 * 4);
        }
        __syncthreads();
        #pragma unroll
        for (int k = 0; k < 32; k++) {
            float2 am = *(float2*)&As[k * 16 + m0];
            float4 wv = *(float4*)&Ws[k * 128 + c0];
            acc[0][0].x += am.x * wv.x; acc[0][0].y += am.x * wv.y;
            acc[0][1].x += am.x * wv.z; acc[0][1].y += am.x * wv.w;
            acc[1][0].x += am.y * wv.x; acc[1][0].y += am.y * wv.y;
            acc[1][1].x += am.y * wv.z; acc[1][1].y += am.y * wv.w;
        }
        __syncthreads();
    }
    #pragma unroll
    for (int im = 0; im < 2; im++) {
        int m = m0 + im;
        float v[4] = {acc[im][0].x, acc[im][0].y, acc[im][1].x, acc[im][1].y};
        #pragma unroll
        for (int jc = 0; jc < 4; jc++)
            g_AW[((size_t)m * H4 + ct * 128 + c0 + jc) * Nn + n] = v[jc];
    }
}

// ---------------- kernel 2: h0 = c0 = mean over Da*Da ----------------
__global__ void __launch_bounds__(256) init_kernel(const float* __restrict__ A) {
    int idx = blockIdx.x * 256 + threadIdx.x;
    int n = idx >> 9, h = idx & 511;
    const float4* p = (const float4*)(A + (size_t)n * (Hh * 16) + h * 16);
    float4 a = p[0], b = p[1], c = p[2], d = p[3];
    float s = a.x + a.y + a.z + a.w + b.x + b.y + b.z + b.w +
              c.x + c.y + c.z + c.w + d.x + d.y + d.z + d.w;
    float v = s * 0.0625f;
    g_Hn[0][n * Hh + h] = v;
    g_HT[0][h * Nn + n] = v;
    g_CT[0][h * Nn + n] = v;
}

// ---------------- kernel 3: x [n][t][k] -> g_XT [t][k][n] ----------------
__global__ void __launch_bounds__(256) xt_kernel(const float* __restrict__ x) {
    __shared__ float tile[32][33];
    const int k0 = blockIdx.x * 32;
    const int t  = blockIdx.y;
    const int tx = threadIdx.x & 31, ty = threadIdx.x >> 5;
    for (int n0 = 0; n0 < Nn; n0 += 32) {
        #pragma unroll
        for (int i = 0; i < 4; i++) {
            int n = ty + i * 8;
            tile[n][tx] = x[((size_t)(n0 + n) * Tt + t) * Dd + k0 + tx];
        }
        __syncthreads();
        #pragma unroll
        for (int i = 0; i < 4; i++) {
            int k = ty + i * 8;
            g_XT[((size_t)t * Dd + k0 + k) * Nn + n0 + tx] = tile[tx][k];
        }
        __syncthreads();
    }
}

// ---------------- kernel 4: pre-splatted per-CTA weights ----------------
// g_WT2[bid][k][cl] = (w,w) where w = W[k][ (cl>>2)*512 + bid*4 + (cl&3) ]
__global__ void __launch_bounds__(256) wt2_kernel(const float* __restrict__ Wx,
                                                  const float* __restrict__ Wh) {
    const int k = blockIdx.x;
    const float* row = (k < 512) ? Wx + (size_t)k * H4 : Wh + (size_t)(k - 512) * H4;
    const int bid = threadIdx.x >> 1, half = threadIdx.x & 1;
    #pragma unroll
    for (int i = 0; i < 8; i++) {
        int cl = half * 8 + i;
        int cg = (cl >> 2) * 512 + bid * 4 + (cl & 3);
        g_WT2[((size_t)bid * KTOT + k) * 16 + cl] = splat2(row[cg]);
    }
}

// ---------------- kernel 5: persistent recurrent kernel ----------------
// dynamic smem (floats):
//   XS0 0, XS1 16384 (each 128k x 128n), WS0 32768, WS1 36864 (each 2048 u64),
//   WSM 40960 (16x128), RED 43008 (128)   -> total 43136 floats = 172544 B
#define XS0 0
#define XS1 16384
#define WS0 32768
#define WS1 36864
#define WSM 40960
#define RED 43008
#define SMEM_BYTES (43136 * 4)

__global__ void __launch_bounds__(256, 2) rnn_kernel(
    const float* __restrict__ A, const float* __restrict__ b4,
    float* __restrict__ out) {

    extern __shared__ float sm[];
    const uint32_t smb = (uint32_t)__cvta_generic_to_shared(sm);
    float* wsm = sm + WSM;
    float* red = sm + RED;

    const int tid = threadIdx.x;
    const int bid = blockIdx.x;
    const int lane = tid & 31, wrp = tid >> 5;

    // Phase A: register-resident Aflat rows (2 per thread)
    float Ar[2][16];
    {
        const float* pA = A + (size_t)bid * (Hh * 16) + (2 * tid) * 16;
        #pragma unroll
        for (int i = 0; i < 16; i++) { Ar[0][i] = pA[i]; Ar[1][i] = pA[16 + i]; }
    }

    // Phase B mapping: ngrp -> 4 n, cgrp -> 2 local cols
    const int ngrp = tid & 31;
    const int cgrp = tid >> 5;
    const int n0 = ngrp * 4;
    const int cl0 = cgrp * 2, cl1 = cgrp * 2 + 1;
    const int cg0 = (cl0 >> 2) * 512 + bid * 4 + (cl0 & 3);
    const int cg1 = (cl1 >> 2) * 512 + bid * 4 + (cl1 & 3);
    const float bb0 = b4[cg0], bb1 = b4[cg1];
    const float inv_sqrt_h = 0.04419417382415922f;   // 1/sqrt(512)

    for (int t = 0; t < Tt; t++) {
        const int p = t & 1;

        // ---- prefetch tile 0 (x) into buffer 0 ----
        {
            const float* src = g_XT + (size_t)t * (Dd * Nn);
            #pragma unroll
            for (int i = 0; i < 16; i++) {
                int ci = tid + i * 256;
                cpa16(smb + XS0 * 4 + ci * 16, src + ci * 4);
            }
            const u64* wsrc = g_WT2 + (size_t)bid * (KTOT * 16);
            #pragma unroll
            for (int i = 0; i < 4; i++) {
                int ci = tid + i * 256;
                cpa16(smb + WS0 * 4 + ci * 16, wsrc + ci * 2);
            }
            cpa_commit();
        }

        // ================= Phase A (overlaps first fill) =================
        {
            float2 hv = *(const float2*)&g_Hn[p][bid * Hh + 2 * tid];
            float part[16];
            #pragma unroll
            for (int m = 0; m < 16; m++)
                part[m] = hv.x * Ar[0][m] + hv.y * Ar[1][m];
            #pragma unroll
            for (int off = 16; off; off >>= 1)
                #pragma unroll
                for (int m = 0; m < 16; m++)
                    part[m] += __shfl_xor_sync(0xffffffffu, part[m], off);
            if (lane == 0) {
                #pragma unroll
                for (int m = 0; m < 16; m++) red[wrp * 16 + m] = part[m];
            }
            __syncthreads();
            if (tid < 16) {
                float sc[16];
                #pragma unroll
                for (int m = 0; m < 16; m++) {
                    float s = 0.f;
                    #pragma unroll
                    for (int w = 0; w < 8; w++) s += red[w * 16 + m];
                    sc[m] = s * inv_sqrt_h;
                }
                float mx = sc[0];
                #pragma unroll
                for (int m = 1; m < 16; m++) mx = fmaxf(mx, sc[m]);
                float se = 0.f;
                #pragma unroll
                for (int m = 0; m < 16; m++) { sc[m] = __expf(sc[m] - mx); se += sc[m]; }
                g_W[tid * Nn + bid] = sc[tid] / se;
            }
        }

        // ================= main GEMM: 8 tiles, cp.async double buffer ========
        u64 a00 = splat2(bb0), a01 = splat2(bb0);
        u64 a10 = splat2(bb1), a11 = splat2(bb1);

        #pragma unroll 1
        for (int j = 0; j < 8; j++) {
            cpa_wait0();
            __syncthreads();
            if (j < 7) {
                int jn = j + 1;
                const float* src = (jn < 4)
                    ? g_XT + (size_t)t * (Dd * Nn) + (size_t)(jn * BK) * Nn
                    : g_HT[p] + (jn - 4) * BK * Nn;
                uint32_t xd = smb + ((jn & 1) ? XS1 : XS0) * 4;
                #pragma unroll
                for (int i = 0; i < 16; i++) {
                    int ci = tid + i * 256;
                    cpa16(xd + ci * 16, src + ci * 4);
                }
                const u64* wsrc = g_WT2 + (size_t)bid * (KTOT * 16) + (size_t)jn * BK * 16;
                uint32_t wd = smb + ((jn & 1) ? WS1 : WS0) * 4;
                #pragma unroll
                for (int i = 0; i < 4; i++) {
                    int ci = tid + i * 256;
                    cpa16(wd + ci * 16, wsrc + ci * 2);
                }
                cpa_commit();
            }
            const float* XsB = sm + ((j & 1) ? XS1 : XS0);
            const u64*   WsB = (const u64*)(sm + ((j & 1) ? WS1 : WS0));
            #pragma unroll 4
            for (int k = 0; k < BK; k++) {
                ulonglong2 xv = *(const ulonglong2*)&XsB[k * 128 + n0];
                ulonglong2 wv = *(const ulonglong2*)&WsB[k * 16 + cl0];
                a00 = ffma2(xv.x, wv.x, a00);
                a01 = ffma2(xv.y, wv.x, a01);
                a10 = ffma2(xv.x, wv.y, a10);
                a11 = ffma2(xv.y, wv.y, a11);
            }
        }

        grid_sync();   // sync1: all CTAs wrote their softmax weights

        // ---- attention contribution: K = 16 ----
        #pragma unroll
        for (int i2 = 0; i2 < 8; i2++) wsm[tid + i2 * 256] = g_W[tid + i2 * 256];
        __syncthreads();
        #pragma unroll
        for (int m = 0; m < 16; m++) {
            ulonglong2 wn = *(const ulonglong2*)&wsm[m * 128 + n0];
            ulonglong2 aw0 = *(const ulonglong2*)(g_AW + ((size_t)m * H4 + cg0) * Nn + n0);
            ulonglong2 aw1 = *(const ulonglong2*)(g_AW + ((size_t)m * H4 + cg1) * Nn + n0);
            a00 = ffma2(aw0.x, wn.x, a00);
            a01 = ffma2(aw0.y, wn.y, a01);
            a10 = ffma2(aw1.x, wn.x, a10);
            a11 = ffma2(aw1.y, wn.y, a11);
        }

        // ---- epilogue: gate exchange via smem (reuse XS0), combine ----
        __syncthreads();
        float* gsm = sm + XS0;   // [16 local cols][128 n]
        *(u64*)&gsm[cl0 * 128 + n0]     = a00;
        *(u64*)&gsm[cl0 * 128 + n0 + 2] = a01;
        *(u64*)&gsm[cl1 * 128 + n0]     = a10;
        *(u64*)&gsm[cl1 * 128 + n0 + 2] = a11;
        __syncthreads();
        if (tid < 128) {
            int nn = tid;
            float hv4[4];
            #pragma unroll
            for (int jj = 0; jj < 4; jj++) {
                float iv = gsm[(0  + jj) * 128 + nn];
                float fv = gsm[(4  + jj) * 128 + nn];
                float ov = gsm[(8  + jj) * 128 + nn];
                float gv = gsm[(12 + jj) * 128 + nn];
                int hcol = bid * 4 + jj;
                float cold = g_CT[p][hcol * Nn + nn];
                float cn = sigmoidf_(fv) * cold + sigmoidf_(iv) * tanhf(gv);
                float hn = sigmoidf_(ov) * tanhf(cn);
                g_CT[p ^ 1][hcol * Nn + nn] = cn;
                g_HT[p ^ 1][hcol * Nn + nn] = hn;
                hv4[jj] = hn;
            }
            *(float4*)&g_Hn[p ^ 1][nn * Hh + bid * 4] = *(float4*)hv4;
            *(float4*)&out[((size_t)nn * Tt + t) * Hh + bid * 4] = *(float4*)hv4;
        }

        grid_sync();   // sync2: new h/c visible for next step
    }
}

// ---------------- launcher ----------------
extern "C" void kernel_launch(void* const* d_in, const int* in_sizes, int n_in,
                              void* d_out, int out_size) {
    const float* x     = (const float*)d_in[0];
    const float* A     = (const float*)d_in[1];
    const float* Wx    = (const float*)d_in[2];
    const float* Wh    = (const float*)d_in[3];
    const float* Wattn = (const float*)d_in[4];
    const float* b     = (const float*)d_in[5];
    float* out = (float*)d_out;
    (void)in_sizes; (void)n_in; (void)out_size;

    cudaFuncSetAttribute(rnn_kernel, cudaFuncAttributeMaxDynamicSharedMemorySize,
                         SMEM_BYTES);

    aw_kernel<<<dim3(16, 128), 256>>>(A, Wattn);
    xt_kernel<<<dim3(16, 512), 256>>>(x);
    wt2_kernel<<<1024, 256>>>(Wx, Wh);
    init_kernel<<<256, 256>>>(A);
    rnn_kernel<<<Nn, 256, SMEM_BYTES>>>(A, b, out);
}

// round 10
// speedup vs baseline: 3.1842x; 2.1482x over previous
#include <cuda_runtime.h>
#include <cuda_bf16.h>
#include <cstdint>

#define Nn 128
#define Tt 512
#define Hh 512
#define H4 2048
typedef unsigned long long u64;
typedef __nv_bfloat16 bf16;

__device__ float g_AW[16 * H4 * Nn];
__device__ bf16  g_Xhi[(size_t)Tt * Nn * 512];
__device__ bf16  g_Xlo[(size_t)Tt * Nn * 512];
__device__ bf16  g_Hhi[2][Nn * 512];
__device__ bf16  g_Hlo[2][Nn * 512];
__device__ float g_Hn[2][Nn * Hh];
__device__ float g_C[Nn * Hh];
__device__ float g_W[16 * Nn];
__device__ unsigned g_cnt = 0, g_gen = 0;

// smem (1024-aligned base): A bufs 4x32768 @0 (per buf: hi 16K + lo 16K, 64k-chunk,
// 128 rows x 128B, SW128). B: Bt[n][k] padded stride 1032 elems, hi @131072,
// lo @164096 (each 33024B). red @197120 (512B).
#define A_OFF 0
#define B_HI  131072
#define B_LO  164096
#define RED_O 197120
#define SMEM_BYTES (197632 + 1024)
#define BSTRIDE 1032

__device__ __forceinline__ uint32_t swz(uint32_t o) { return o ^ ((o >> 3) & 0x70); }
__device__ __forceinline__ float sigmoidf_(float v) { return 1.0f / (1.0f + __expf(-v)); }
__device__ __forceinline__ void cpa16(uint32_t d, const void* s) {
    asm volatile("cp.async.cg.shared.global [%0], [%1], 16;" :: "r"(d), "l"(s));
}
#define CPA_COMMIT() asm volatile("cp.async.commit_group;")
#define CPA_WAIT(n)  asm volatile("cp.async.wait_group %0;" :: "n"(n))

__device__ __forceinline__ void ldsm4(uint32_t* r, uint32_t a) {
    asm volatile("ldmatrix.sync.aligned.m8n8.x4.shared.b16 {%0,%1,%2,%3}, [%4];"
        : "=r"(r[0]), "=r"(r[1]), "=r"(r[2]), "=r"(r[3]) : "r"(a));
}
__device__ __forceinline__ void ldsm2(uint32_t* r, uint32_t a) {
    asm volatile("ldmatrix.sync.aligned.m8n8.x2.shared.b16 {%0,%1}, [%2];"
        : "=r"(r[0]), "=r"(r[1]) : "r"(a));
}
__device__ __forceinline__ void hmma(float* d, const uint32_t* a, const uint32_t* b) {
    asm volatile("mma.sync.aligned.m16n8k16.row.col.f32.bf16.bf16.f32 "
        "{%0,%1,%2,%3}, {%4,%5,%6,%7}, {%8,%9}, {%0,%1,%2,%3};"
        : "+f"(d[0]), "+f"(d[1]), "+f"(d[2]), "+f"(d[3])
        : "r"(a[0]), "r"(a[1]), "r"(a[2]), "r"(a[3]), "r"(b[0]), "r"(b[1]));
}
__device__ __forceinline__ void grid_sync() {
    __syncthreads();
    if (threadIdx.x == 0) {
        __threadfence();
        unsigned gen = *((volatile unsigned*)&g_gen);
        if (atomicAdd(&g_cnt, 1u) == Nn - 1) {
            atomicExch(&g_cnt, 0u); __threadfence(); atomicAdd(&g_gen, 1u);
        } else {
            while (*((volatile unsigned*)&g_gen) == gen) __nanosleep(32);
        }
        __threadfence();
    }
    __syncthreads();
}

// ---- AW[m][c][n] = sum_h Aflat[n][h][m] * Wattn[h][c] ----
__global__ void __launch_bounds__(256) aw_kernel(const float* __restrict__ A,
                                                 const float* __restrict__ Wattn) {
    __shared__ float As[512], Ws[32 * 128];
    const int tid = threadIdx.x, ct = blockIdx.x, n = blockIdx.y;
    const int tx = tid & 31, ty = tid >> 5, m0 = ty * 2, c0 = tx * 4;
    float acc[2][4] = {};
    for (int h0 = 0; h0 < Hh; h0 += 32) {
        const float* sA = A + (size_t)n * (Hh * 16) + h0 * 16;
        As[tid] = sA[tid]; As[tid + 256] = sA[tid + 256];
        #pragma unroll
        for (int j = 0; j < 4; j++) {
            int fi = tid + j * 256, r = fi >> 5, c4 = fi & 31;
            *(float4*)&Ws[r * 128 + c4 * 4] =
                *(const float4*)(Wattn + (size_t)(h0 + r) * H4 + ct * 128 + c4 * 4);
        }
        __syncthreads();
        #pragma unroll
        for (int k = 0; k < 32; k++) {
            float2 am = *(float2*)&As[k * 16 + m0];
            float4 wv = *(float4*)&Ws[k * 128 + c0];
            acc[0][0] += am.x * wv.x; acc[0][1] += am.x * wv.y;
            acc[0][2] += am.x * wv.z; acc[0][3] += am.x * wv.w;
            acc[1][0] += am.y * wv.x; acc[1][1] += am.y * wv.y;
            acc[1][2] += am.y * wv.z; acc[1][3] += am.y * wv.w;
        }
        __syncthreads();
    }
    #pragma unroll
    for (int im = 0; im < 2; im++)
        #pragma unroll
        for (int jc = 0; jc < 4; jc++)
            g_AW[((size_t)(m0 + im) * H4 + ct * 128 + c0 + jc) * Nn + n] = acc[im][jc];
}

// ---- bf16 hi/lo split of x into [t][n][k] ----
__global__ void __launch_bounds__(256) xbf_kernel(const float* __restrict__ x) {
    const int t = blockIdx.x >> 7, n = blockIdx.x & 127, k = threadIdx.x * 2;
    float2 v = *(const float2*)&x[((size_t)n * Tt + t) * 512 + k];
    bf16 h0 = __float2bfloat16(v.x), h1 = __float2bfloat16(v.y);
    bf16 l0 = __float2bfloat16(v.x - __bfloat162float(h0));
    bf16 l1 = __float2bfloat16(v.y - __bfloat162float(h1));
    size_t o = ((size_t)t * Nn + n) * 512 + k;
    *(__nv_bfloat162*)&g_Xhi[o] = __nv_bfloat162(h0, h1);
    *(__nv_bfloat162*)&g_Xlo[o] = __nv_bfloat162(l0, l1);
}

// ---- h0 = c0 = mean over Da*Da ----
__global__ void __launch_bounds__(256) init_kernel(const float* __restrict__ A) {
    int idx = blockIdx.x * 256 + threadIdx.x;
    int n = idx >> 9, h = idx & 511;
    const float4* p = (const float4*)(A + (size_t)n * (Hh * 16) + h * 16);
    float4 a = p[0], b = p[1], c = p[2], d = p[3];
    float v = (a.x + a.y + a.z + a.w + b.x + b.y + b.z + b.w +
               c.x + c.y + c.z + c.w + d.x + d.y + d.z + d.w) * 0.0625f;
    g_Hn[0][n * Hh + h] = v;
    g_C[n * Hh + h] = v;
    bf16 hi = __float2bfloat16(v);
    g_Hhi[0][n * 512 + h] = hi;
    g_Hlo[0][n * 512 + h] = __float2bfloat16(v - __bfloat162float(hi));
}

// ---- persistent recurrent kernel (mma.sync bf16 3-term) ----
__global__ void __launch_bounds__(256, 1) rnn_kernel(
    const float* __restrict__ A, const float* __restrict__ Wx,
    const float* __restrict__ Wh, const float* __restrict__ b4,
    float* __restrict__ out) {

    extern __shared__ char smraw[];
    char* smc = (char*)(((uintptr_t)smraw + 1023) & ~(uintptr_t)1023);
    const uint32_t smb = (uint32_t)__cvta_generic_to_shared(smc);
    float* red = (float*)(smc + RED_O);
    const int tid = threadIdx.x, bid = blockIdx.x;
    const int wid = tid >> 5, lane = tid & 31, bid4 = bid * 4;
    const int gid = lane >> 2, tig = lane & 3;

    // B resident: Bt[n][k] hi+lo, padded stride (conflict-free frag loads)
    for (int e = 0; e < 64; e++) {
        int idx = tid + e * 256;
        int n = idx >> 10, k = idx & 1023;
        int cgc = (n >> 2) * 512 + bid4 + (n & 3);
        float v = (k < 512) ? Wx[(size_t)k * H4 + cgc] : Wh[(size_t)(k - 512) * H4 + cgc];
        bf16 hi = __float2bfloat16(v);
        bf16 lo = __float2bfloat16(v - __bfloat162float(hi));
        *(bf16*)(smc + B_HI + (n * BSTRIDE + k) * 2) = hi;
        *(bf16*)(smc + B_LO + (n * BSTRIDE + k) * 2) = lo;
    }
    __syncthreads();

    float Ar[2][16];
    {
        const float* pA = A + (size_t)bid * (Hh * 16) + (2 * tid) * 16;
        #pragma unroll
        for (int i = 0; i < 16; i++) { Ar[0][i] = pA[i]; Ar[1][i] = pA[16 + i]; }
    }
    float bb[16];
    #pragma unroll
    for (int cl = 0; cl < 16; cl++) bb[cl] = b4[(cl >> 2) * 512 + bid4 + (cl & 3)];
    const float inv_sqrt_h = 0.04419417382415922f;

    // per-thread ldmatrix A address pieces: row = wid*16 + (lane&15), cb = (lane>>4)*16
    const uint32_t a_row = wid * 16 + (lane & 15);
    const uint32_t a_cb  = (lane >> 4) * 16;
    // B frag addr pieces (t<16 meaningful): row n' = (lane&7), koff8 = ((lane>>3)&1)*8
    const uint32_t b_nr = lane & 7, b_k8 = ((lane >> 3) & 1) * 8;

    for (int t = 0; t < Tt; t++) {
        const int p = t & 1;

        auto fill = [&](int ck, int bf) {
            const bf16* hb, * lb;
            if (ck < 8) {
                size_t base = (size_t)t * (Nn * 512) + ck * 64;
                hb = g_Xhi + base; lb = g_Xlo + base;
            } else {
                size_t base = (size_t)(ck - 8) * 64;
                hb = g_Hhi[p] + base; lb = g_Hlo[p] + base;
            }
            uint32_t dst0 = smb + A_OFF + bf * 32768;
            #pragma unroll
            for (int it = 0; it < 8; it++) {
                int ci = tid + it * 256;
                int term = ci >> 10, g = ci & 1023;
                int row = g >> 3, c16 = g & 7;
                cpa16(dst0 + term * 16384 + swz((uint32_t)(row * 128 + c16 * 16)),
                      (term ? lb : hb) + (size_t)row * 512 + c16 * 8);
            }
            CPA_COMMIT();
        };

        fill(0, 0); fill(1, 1); fill(2, 2);

        // Phase A (overlaps fills): softmax attention weights
        {
            float2 hv = *(const float2*)&g_Hn[p][bid * Hh + 2 * tid];
            float part[16];
            #pragma unroll
            for (int m = 0; m < 16; m++) part[m] = hv.x * Ar[0][m] + hv.y * Ar[1][m];
            #pragma unroll
            for (int off = 16; off; off >>= 1)
                #pragma unroll
                for (int m = 0; m < 16; m++)
                    part[m] += __shfl_xor_sync(0xffffffffu, part[m], off);
            if (lane == 0) {
                #pragma unroll
                for (int m = 0; m < 16; m++) red[wid * 16 + m] = part[m];
            }
            __syncthreads();
            if (tid < 16) {
                float sc[16];
                #pragma unroll
                for (int m = 0; m < 16; m++) {
                    float s = 0.f;
                    #pragma unroll
                    for (int w = 0; w < 8; w++) s += red[w * 16 + m];
                    sc[m] = s * inv_sqrt_h;
                }
                float mx = sc[0];
                #pragma unroll
                for (int m = 1; m < 16; m++) mx = fmaxf(mx, sc[m]);
                float se = 0.f;
                #pragma unroll
                for (int m = 0; m < 16; m++) { sc[m] = __expf(sc[m] - mx); se += sc[m]; }
                g_W[tid * Nn + bid] = sc[tid] / se;
            }
        }

        float d[2][4] = {};   // [ntile][frag]

        // main chunk loop: 16 chunks of 64k
        #pragma unroll 1
        for (int c = 0; c < 16; c++) {
            if (c < 14) CPA_WAIT(2);
            else if (c == 14) CPA_WAIT(1);
            else CPA_WAIT(0);
            __syncthreads();
            if (c < 13) fill(c + 3, (c + 3) & 3);
            uint32_t ab = smb + A_OFF + (c & 3) * 32768;
            #pragma unroll
            for (int kt = 0; kt < 4; kt++) {
                uint32_t afh[4], afl[4];
                uint32_t aoff = swz((uint32_t)(a_row * 128 + kt * 32 + a_cb));
                ldsm4(afh, ab + aoff);
                ldsm4(afl, ab + 16384 + aoff);
                int kg = c * 64 + kt * 16;   // global k of this tile
                #pragma unroll
                for (int nt = 0; nt < 2; nt++) {
                    uint32_t boff = ((nt * 8 + b_nr) * BSTRIDE + kg + b_k8) * 2;
                    uint32_t bfh[2], bfl[2];
                    ldsm2(bfh, smb + B_HI + boff);
                    ldsm2(bfl, smb + B_LO + boff);
                    hmma(d[nt], afh, bfh);
                    hmma(d[nt], afh, bfl);
                    hmma(d[nt], afl, bfh);
                }
            }
        }

        grid_sync();   // sync1: g_W from all CTAs visible

        // scatter fragments to gsm[cl][row] (reuse A buf 0)
        float* gsm = (float*)(smc + A_OFF);
        #pragma unroll
        for (int nt = 0; nt < 2; nt++) {
            int cl = nt * 8 + tig * 2;
            int r0 = wid * 16 + gid;
            gsm[(cl + 0) * 128 + r0]     = d[nt][0];
            gsm[(cl + 1) * 128 + r0]     = d[nt][1];
            gsm[(cl + 0) * 128 + r0 + 8] = d[nt][2];
            gsm[(cl + 1) * 128 + r0 + 8] = d[nt][3];
            d[nt][0] = d[nt][1] = d[nt][2] = d[nt][3] = 0.f;
        }
        __syncthreads();

        // gates + attn: thread tid = batch row n (tid < 128)
        if (tid < 128) {
            const int n = tid;
            float dd[16];
            #pragma unroll
            for (int cl = 0; cl < 16; cl++) dd[cl] = gsm[cl * 128 + n] + bb[cl];
            #pragma unroll
            for (int m = 0; m < 16; m++) {
                float wm = g_W[m * Nn + n];
                #pragma unroll
                for (int cl = 0; cl < 16; cl++)
                    dd[cl] += g_AW[((size_t)m * H4 + (cl >> 2) * 512 + bid4 + (cl & 3)) * Nn + n] * wm;
            }
            float4 cold = *(float4*)&g_C[n * Hh + bid4];
            float co[4] = {cold.x, cold.y, cold.z, cold.w};
            float hv4[4];
            ushort4 hhi, hlo;
            unsigned short* hip = (unsigned short*)&hhi;
            unsigned short* lop = (unsigned short*)&hlo;
            #pragma unroll
            for (int j = 0; j < 4; j++) {
                float cn = sigmoidf_(dd[4 + j]) * co[j] + sigmoidf_(dd[0 + j]) * tanhf(dd[12 + j]);
                float hn = sigmoidf_(dd[8 + j]) * tanhf(cn);
                co[j] = cn; hv4[j] = hn;
                bf16 hb = __float2bfloat16(hn);
                bf16 lb = __float2bfloat16(hn - __bfloat162float(hb));
                hip[j] = *(unsigned short*)&hb;
                lop[j] = *(unsigned short*)&lb;
            }
            *(float4*)&g_C[n * Hh + bid4] = make_float4(co[0], co[1], co[2], co[3]);
            *(ushort4*)&g_Hhi[p ^ 1][n * 512 + bid4] = hhi;
            *(ushort4*)&g_Hlo[p ^ 1][n * 512 + bid4] = hlo;
            *(float4*)&g_Hn[p ^ 1][n * Hh + bid4] = *(float4*)hv4;
            *(float4*)&out[((size_t)n * Tt + t) * Hh + bid4] = *(float4*)hv4;
        }

        grid_sync();   // sync2: new h/c visible for next step
    }
}

extern "C" void kernel_launch(void* const* d_in, const int* in_sizes, int n_in,
                              void* d_out, int out_size) {
    const float* x     = (const float*)d_in[0];
    const float* A     = (const float*)d_in[1];
    const float* Wx    = (const float*)d_in[2];
    const float* Wh    = (const float*)d_in[3];
    const float* Wattn = (const float*)d_in[4];
    const float* b     = (const float*)d_in[5];
    float* out = (float*)d_out;
    (void)in_sizes; (void)n_in; (void)out_size;

    cudaFuncSetAttribute(rnn_kernel, cudaFuncAttributeMaxDynamicSharedMemorySize, SMEM_BYTES);
    aw_kernel<<<dim3(16, 128), 256>>>(A, Wattn);
    xbf_kernel<<<Tt * Nn, 256>>>(x);
    init_kernel<<<256, 256>>>(A);
    rnn_kernel<<<Nn, 256, SMEM_BYTES>>>(A, Wx, Wh, b, out);
}